// round 2
// baseline (speedup 1.0000x reference)
#include <cuda_runtime.h>
#include <cstdint>
#include <math.h>

#define BATCH 16
#define CIN   512
#define OC    512
#define HH    38
#define WW    50
#define HWP   (HH*WW)          // 1900
#define NPIX  (BATCH*HWP)      // 30400
#define KTOT  (CIN*9)          // 4608
#define NA    9
#define NANCH (HWP*NA)         // 17100
#define PRE   6000
#define POST  300
#define PRE_PAD 8192
#define CAND_PAD 6016
#define IMG_HF 608.0f
#define IMG_WF 800.0f
#define MIN_SZ 16.0f
#define NMS_T  0.7f

// ---------------- scratch (device globals; no allocation allowed) ----------
__device__ float  g_shared[(size_t)BATCH * OC * HWP];   // conv3x3 output (relu)
__device__ float4 g_boxes[BATCH * NANCH];               // clipped boxes y1x1y2x2
__device__ float  g_scores[BATCH * NANCH];              // fg score or -inf

// anchor base (double-precision values rounded to fp32, chainercv layout y1x1y2x2)
__constant__ float c_ab[9][4] = {
    {-37.254833995939044f,  -82.50966799187809f,   53.254833995939044f,  98.50966799187809f},
    {-82.50966799187809f,  -173.01933598375618f,   98.50966799187809f,  189.01933598375618f},
    {-173.01933598375618f, -354.03867196751234f,  189.01933598375618f,  370.03867196751234f},
    {-56.0f,  -56.0f,   72.0f,   72.0f},
    {-120.0f, -120.0f, 136.0f,  136.0f},
    {-248.0f, -248.0f, 264.0f,  264.0f},
    {-82.50966799187809f,   -37.254833995939044f,  98.50966799187809f,   53.254833995939044f},
    {-173.01933598375618f,  -82.50966799187809f,  189.01933598375618f,   98.50966799187809f},
    {-354.03867196751234f, -173.01933598375618f,  370.03867196751234f,  189.01933598375618f},
};

// ================= 1) conv3x3 + bias + relu as implicit GEMM ================
// C[m, n] = sum_k W[m,k] * im2col(X)[k,n];  m = oc (512), n = b*1900+p (30400),
// k = ic*9 + ky*3 + kx (4608).  BM=BN=64, BK=16, 4x4 thread tile, 256 threads.
// Accumulation: per-BK chunk into fresh registers, Kahan-merged into the
// running sum -> relative error ~3 eps instead of ~34 eps (serial chain).
__global__ __launch_bounds__(256) void conv3x3_kernel(
    const float* __restrict__ x, const float* __restrict__ wgt,
    const float* __restrict__ bias)
{
    __shared__ float As[16][64];   // As[k][m]
    __shared__ float Bs[16][64];   // Bs[k][n]

    const int tid = threadIdx.x;
    const int n0  = blockIdx.x * 64;
    const int m0  = blockIdx.y * 64;

    // --- B (im2col) loader precompute: thread loads (b_k, 4 consecutive n) ---
    const int b_k = tid >> 4;            // 0..15
    const int b_n = (tid & 15) * 4;      // 0..60
    int nbase[4], nyv[4], nxv[4];
#pragma unroll
    for (int u = 0; u < 4; u++) {
        int n  = n0 + b_n + u;
        int bi = n / HWP;
        int p  = n - bi * HWP;
        int y  = p / WW;
        int xq = p - y * WW;
        nyv[u] = y; nxv[u] = xq;
        nbase[u] = bi * (CIN * HWP);
    }
    // --- A loader: thread loads float4 along k for one m ---
    const int a_m = tid >> 2;            // 0..63
    const int a_k = (tid & 3) * 4;       // 0,4,8,12
    const float* aptr = wgt + (size_t)(m0 + a_m) * KTOT + a_k;

    const int tx = tid & 15;             // n-tile
    const int ty = tid >> 4;             // m-tile

    float acc[4][4], cmp[4][4];
#pragma unroll
    for (int i = 0; i < 4; i++)
#pragma unroll
        for (int j = 0; j < 4; j++) { acc[i][j] = 0.0f; cmp[i][j] = 0.0f; }

    for (int k0 = 0; k0 < KTOT; k0 += 16) {
        // load A tile (transposed into As[k][m])
        float4 av = *(const float4*)(aptr + k0);
        As[a_k + 0][a_m] = av.x;
        As[a_k + 1][a_m] = av.y;
        As[a_k + 2][a_m] = av.z;
        As[a_k + 3][a_m] = av.w;

        // load B tile (im2col on the fly)
        int kg  = k0 + b_k;
        int ic  = kg / 9;
        int rem = kg - ic * 9;
        int ky  = rem / 3;
        int kx  = rem - ky * 3;
        int dy = ky - 1, dx = kx - 1;
        float bv[4];
#pragma unroll
        for (int u = 0; u < 4; u++) {
            int iy = nyv[u] + dy;
            int ix = nxv[u] + dx;
            bool ok = ((unsigned)iy < (unsigned)HH) && ((unsigned)ix < (unsigned)WW);
            bv[u] = ok ? x[nbase[u] + ic * HWP + iy * WW + ix] : 0.0f;
        }
        *(float4*)(&Bs[b_k][b_n]) = make_float4(bv[0], bv[1], bv[2], bv[3]);

        __syncthreads();
        float ch[4][4];
#pragma unroll
        for (int i = 0; i < 4; i++)
#pragma unroll
            for (int j = 0; j < 4; j++) ch[i][j] = 0.0f;
#pragma unroll
        for (int kk = 0; kk < 16; kk++) {
            float4 a4 = *(const float4*)(&As[kk][ty * 4]);
            float4 b4 = *(const float4*)(&Bs[kk][tx * 4]);
            float ar[4] = {a4.x, a4.y, a4.z, a4.w};
            float br[4] = {b4.x, b4.y, b4.z, b4.w};
#pragma unroll
            for (int i = 0; i < 4; i++)
#pragma unroll
                for (int j = 0; j < 4; j++) ch[i][j] += ar[i] * br[j];
        }
        // Kahan-merge chunk sum into running accumulator
#pragma unroll
        for (int i = 0; i < 4; i++)
#pragma unroll
            for (int j = 0; j < 4; j++) {
                float y = ch[i][j] - cmp[i][j];
                float t = acc[i][j] + y;
                cmp[i][j] = (t - acc[i][j]) - y;
                acc[i][j] = t;
            }
        __syncthreads();
    }

    // epilogue: +bias, relu, store to g_shared[b][oc][p]
#pragma unroll
    for (int i = 0; i < 4; i++) {
        int m = m0 + ty * 4 + i;
        float bb = bias[m];
#pragma unroll
        for (int j = 0; j < 4; j++) {
            int n  = n0 + tx * 4 + j;
            int bi = n / HWP;
            int p  = n - bi * HWP;
            float v = acc[i][j] + bb;
            v = fmaxf(v, 0.0f);
            g_shared[((size_t)bi * OC + m) * HWP + p] = v;
        }
    }
}

// ======= 2) fused 1x1 heads + softmax + decode + clip + min-size mask =======
// block = 32 pixels x 8 row-groups (54 output rows: 0..17 cls, 18..53 reg)
// K=512 dot products: chunk-16 partial sums Kahan-merged (error ~3 eps).
__global__ __launch_bounds__(256) void head_kernel(
    const float* __restrict__ clsw, const float* __restrict__ clsb,
    const float* __restrict__ regw, const float* __restrict__ regb)
{
    __shared__ float vals[54][33];

    const int tid = threadIdx.x;
    const int px  = tid & 31;
    const int r0  = tid >> 5;          // 0..7
    const int n   = blockIdx.x * 32 + px;
    const int bi  = n / HWP;
    const int p   = n - bi * HWP;

    const float* act = g_shared + (size_t)bi * OC * HWP + p;

    const int gcount = (r0 < 6) ? 7 : 6;
    float acc[7], cmp[7], bias0[7];
    const float* wrow[7];
#pragma unroll
    for (int g = 0; g < 7; g++) {
        acc[g] = 0.0f; cmp[g] = 0.0f; bias0[g] = 0.0f; wrow[g] = clsw;
        if (g < gcount) {
            int r = r0 + 8 * g;
            if (r < 18) { bias0[g] = clsb[r];      wrow[g] = clsw + r * 512; }
            else        { bias0[g] = regb[r - 18]; wrow[g] = regw + (r - 18) * 512; }
        }
    }

    for (int k0 = 0; k0 < 512; k0 += 16) {
        float ch[7];
#pragma unroll
        for (int g = 0; g < 7; g++) ch[g] = 0.0f;
#pragma unroll
        for (int kk = 0; kk < 16; kk++) {
            float a = act[(size_t)(k0 + kk) * HWP];
#pragma unroll
            for (int g = 0; g < 7; g++)
                if (g < gcount) ch[g] += wrow[g][k0 + kk] * a;
        }
#pragma unroll
        for (int g = 0; g < 7; g++) {
            float y = ch[g] - cmp[g];
            float t = acc[g] + y;
            cmp[g] = (t - acc[g]) - y;
            acc[g] = t;
        }
    }
#pragma unroll
    for (int g = 0; g < 7; g++)
        if (g < gcount) vals[r0 + 8 * g][px] = acc[g] + bias0[g];
    __syncthreads();

    if (tid < 32) {
        // softmax over 18 cls channels (max-subtracted, matches jax.nn.softmax)
        float mx = vals[0][px];
#pragma unroll
        for (int c = 1; c < 18; c++) mx = fmaxf(mx, vals[c][px]);
        float sum = 0.0f;
#pragma unroll
        for (int c = 0; c < 18; c++) sum += expf(vals[c][px] - mx);

        int y  = p / WW;
        int xq = p - y * WW;
        float sy = (float)(y  * 16);
        float sx = (float)(xq * 16);

#pragma unroll
        for (int a = 0; a < 9; a++) {
            float score = expf(vals[2 * a + 1][px] - mx) / sum;
            float dy = vals[18 + 4 * a + 0][px];
            float dx = vals[18 + 4 * a + 1][px];
            float dh = vals[18 + 4 * a + 2][px];
            float dw = vals[18 + 4 * a + 3][px];

            float ay1 = sy + c_ab[a][0];
            float ax1 = sx + c_ab[a][1];
            float ay2 = sy + c_ab[a][2];
            float ax2 = sx + c_ab[a][3];
            float ah  = ay2 - ay1;
            float aw  = ax2 - ax1;
            float acy = ay1 + 0.5f * ah;
            float acx = ax1 + 0.5f * aw;
            float cy  = dy * ah + acy;
            float cx  = dx * aw + acx;
            float h2  = expf(dh) * ah;
            float w2  = expf(dw) * aw;
            float y1 = cy - 0.5f * h2, x1 = cx - 0.5f * w2;
            float y2 = cy + 0.5f * h2, x2 = cx + 0.5f * w2;
            // clip to image
            y1 = fminf(fmaxf(y1, 0.0f), IMG_HF);
            x1 = fminf(fmaxf(x1, 0.0f), IMG_WF);
            y2 = fminf(fmaxf(y2, 0.0f), IMG_HF);
            x2 = fminf(fmaxf(x2, 0.0f), IMG_WF);
            float hs = y2 - y1, ws = x2 - x1;
            if (!(hs >= MIN_SZ && ws >= MIN_SZ)) score = -INFINITY;

            int idx = bi * NANCH + p * 9 + a;
            g_boxes[idx]  = make_float4(y1, x1, y2, x2);
            g_scores[idx] = score;
        }
    }
}

// ================= 3) per-image top-6000 + greedy NMS =======================
__device__ __forceinline__ unsigned long long make_key(float s, int i) {
    unsigned int ub  = __float_as_uint(s);
    unsigned int ord = (ub & 0x80000000u) ? ~ub : (ub | 0x80000000u);
    return ((unsigned long long)ord << 32) |
           (unsigned long long)(0xFFFFFFFFu - (unsigned)i);
}

__global__ __launch_bounds__(1024) void nms_kernel(float* __restrict__ out)
{
    extern __shared__ char smraw[];
    unsigned long long* keys = (unsigned long long*)smraw;                 // 8192
    float* by1 = (float*)(smraw + PRE_PAD * 8);
    float* bx1 = by1 + CAND_PAD;
    float* by2 = bx1 + CAND_PAD;
    float* bx2 = by2 + CAND_PAD;
    float* bar = bx2 + CAND_PAD;
    float* bsc = bar + CAND_PAD;
    unsigned char* valid = (unsigned char*)(bsc + CAND_PAD);

    __shared__ unsigned int hist[256];
    __shared__ unsigned long long prefix_s;
    __shared__ int rank_s, cnt_s, sel_s, cur_s;

    const int img = blockIdx.x;
    const int tid = threadIdx.x;
    const float* sc = g_scores + img * NANCH;

    if (tid == 0) { prefix_s = 0ULL; rank_s = PRE; cnt_s = 0; cur_s = 0; }
    __syncthreads();

    // --- exact 64-bit radix-select of the PRE-th largest key (keys distinct) ---
    for (int byte = 7; byte >= 0; byte--) {
        if (tid < 256) hist[tid] = 0u;
        __syncthreads();
        unsigned long long pre = prefix_s;
        for (int i = tid; i < NANCH; i += 1024) {
            unsigned long long key = make_key(sc[i], i);
            bool match = (byte == 7) ||
                ((key >> ((byte + 1) * 8)) == (pre >> ((byte + 1) * 8)));
            if (match) atomicAdd(&hist[(unsigned)(key >> (byte * 8)) & 255u], 1u);
        }
        __syncthreads();
        if (tid == 0) {
            int rank = rank_s;
            int d = 255;
            for (; d > 0; d--) {
                int c = (int)hist[d];
                if (c >= rank) break;
                rank -= c;
            }
            rank_s   = rank;
            prefix_s = prefix_s | ((unsigned long long)(unsigned)d << (byte * 8));
        }
        __syncthreads();
    }
    const unsigned long long T = prefix_s;

    // --- compact the exactly-PRE keys >= T, pad to PRE_PAD ---
    for (int i = tid; i < NANCH; i += 1024) {
        unsigned long long key = make_key(sc[i], i);
        if (key >= T) {
            int pos = atomicAdd(&cnt_s, 1);
            if (pos < PRE_PAD) keys[pos] = key;
        }
    }
    __syncthreads();
    int cnt = cnt_s; if (cnt > PRE_PAD) cnt = PRE_PAD;
    for (int i = tid; i < PRE_PAD; i += 1024)
        if (i >= cnt) keys[i] = 0ULL;
    __syncthreads();

    // --- bitonic sort descending (8192 u64 keys in smem) ---
    for (int k = 2; k <= PRE_PAD; k <<= 1) {
        for (int j = k >> 1; j >= 1; j >>= 1) {
            for (int t = tid; t < PRE_PAD; t += 1024) {
                int l = t ^ j;
                if (l > t) {
                    unsigned long long a = keys[t], b = keys[l];
                    bool seg = ((t & k) == 0);
                    if (seg ? (a < b) : (a > b)) { keys[t] = b; keys[l] = a; }
                }
            }
            __syncthreads();
        }
    }

    // --- gather sorted candidates into SoA smem ---
    for (int jj = tid; jj < PRE; jj += 1024) {
        unsigned long long key = keys[jj];
        if (key == 0ULL) {  // safety: fewer than PRE real candidates
            by1[jj] = bx1[jj] = by2[jj] = bx2[jj] = bar[jj] = bsc[jj] = 0.0f;
            valid[jj] = 0;
            continue;
        }
        unsigned int low = (unsigned int)key;
        int i = (int)(0xFFFFFFFFu - low);
        float4 bx = g_boxes[img * NANCH + i];
        by1[jj] = bx.x; bx1[jj] = bx.y; by2[jj] = bx.z; bx2[jj] = bx.w;
        bar[jj] = fmaxf(bx.z - bx.x, 0.0f) * fmaxf(bx.w - bx.y, 0.0f);
        unsigned int ou = (unsigned int)(key >> 32);
        unsigned int fb = (ou & 0x80000000u) ? (ou & 0x7FFFFFFFu) : ~ou;
        float s = __uint_as_float(fb);
        bsc[jj]   = s;
        valid[jj] = isfinite(s) ? 1 : 0;
    }
    __syncthreads();

    // --- greedy NMS walk over the sorted list (== repeated argmax) ---
    float* o = out + (size_t)img * POST * 5;
    for (int t = 0; t < POST; t++) {
        if (tid == 0) {
            int c = cur_s;
            while (c < PRE && !valid[c]) c++;
            if (c < PRE) { valid[c] = 0; sel_s = c; cur_s = c + 1; }
            else sel_s = -1;
        }
        __syncthreads();
        int sel = sel_s;
        if (sel < 0) {   // out of valid candidates -> zero remaining rows
            for (int e = t * 5 + tid; e < POST * 5; e += 1024) o[e] = 0.0f;
            break;
        }
        float sy1 = by1[sel], sx1 = bx1[sel], sy2 = by2[sel], sx2 = bx2[sel];
        float sa  = bar[sel];
        for (int j = tid; j < PRE; j += 1024) {
            if (valid[j]) {
                float yy1 = fmaxf(sy1, by1[j]);
                float xx1 = fmaxf(sx1, bx1[j]);
                float yy2 = fminf(sy2, by2[j]);
                float xx2 = fminf(sx2, bx2[j]);
                float inter = fmaxf(yy2 - yy1, 0.0f) * fmaxf(xx2 - xx1, 0.0f);
                float iou = inter / (bar[j] + sa - inter + 1e-9f);
                if (iou > NMS_T) valid[j] = 0;
            }
        }
        if (tid == 0) {
            o[t * 5 + 0] = sy1; o[t * 5 + 1] = sx1;
            o[t * 5 + 2] = sy2; o[t * 5 + 3] = sx2;
            o[t * 5 + 4] = bsc[sel];
        }
        __syncthreads();
    }
}

// ============================== launch ======================================
extern "C" void kernel_launch(void* const* d_in, const int* in_sizes, int n_in,
                              void* d_out, int out_size)
{
    const float* x  = (const float*)d_in[0];
    const float* sw = (const float*)d_in[1];
    const float* sb = (const float*)d_in[2];
    const float* cw = (const float*)d_in[3];
    const float* cb = (const float*)d_in[4];
    const float* rw = (const float*)d_in[5];
    const float* rb = (const float*)d_in[6];
    float* out = (float*)d_out;

    conv3x3_kernel<<<dim3(NPIX / 64, OC / 64), 256>>>(x, sw, sb);
    head_kernel<<<NPIX / 32, 256>>>(cw, cb, rw, rb);

    const int nms_smem = PRE_PAD * 8 + 6 * CAND_PAD * 4 + CAND_PAD;  // 215936 B
    cudaFuncSetAttribute(nms_kernel,
                         cudaFuncAttributeMaxDynamicSharedMemorySize, nms_smem);
    nms_kernel<<<BATCH, 1024, nms_smem>>>(out);
}

// round 4
// speedup vs baseline: 1.1101x; 1.1101x over previous
#include <cuda_runtime.h>
#include <cstdint>
#include <string.h>
#include <math.h>

#define BATCH 16
#define CIN   512
#define OC    512
#define HH    38
#define WW    50
#define HWP   (HH*WW)          // 1900
#define NPIX  (BATCH*HWP)      // 30400
#define KTOT  (CIN*9)          // 4608
#define NA    9
#define NANCH (HWP*NA)         // 17100
#define PRE   6000
#define POST  300
#define PRE_PAD 8192
#define CAND_PAD 6016
#define IMG_HF 608.0f
#define IMG_WF 800.0f
#define MIN_SZ 16.0f
#define NMS_T  0.7f

#define BM 128
#define BN 128
#define BK 8
#define CITERS (KTOT/BK)       // 576

// ---------------- scratch (device globals; no allocation allowed) ----------
__device__ float  g_shared[(size_t)BATCH * OC * HWP];   // conv3x3 output (relu)
__device__ float4 g_boxes[BATCH * NANCH];               // clipped boxes y1x1y2x2
__device__ float  g_scores[BATCH * NANCH];              // fg score or -inf

// anchor base (double-precision values rounded to fp32, chainercv layout y1x1y2x2)
__constant__ float c_ab[9][4] = {
    {-37.254833995939044f,  -82.50966799187809f,   53.254833995939044f,  98.50966799187809f},
    {-82.50966799187809f,  -173.01933598375618f,   98.50966799187809f,  189.01933598375618f},
    {-173.01933598375618f, -354.03867196751234f,  189.01933598375618f,  370.03867196751234f},
    {-56.0f,  -56.0f,   72.0f,   72.0f},
    {-120.0f, -120.0f, 136.0f,  136.0f},
    {-248.0f, -248.0f, 264.0f,  264.0f},
    {-82.50966799187809f,   -37.254833995939044f,  98.50966799187809f,   53.254833995939044f},
    {-173.01933598375618f,  -82.50966799187809f,  189.01933598375618f,   98.50966799187809f},
    {-354.03867196751234f, -173.01933598375618f,  370.03867196751234f,  189.01933598375618f},
};

// ---------------- packed f32x2 helpers -------------------------------------
typedef unsigned long long ull;

__device__ __forceinline__ ull fma2(ull a, ull b, ull c) {
    ull d;
    asm("fma.rn.f32x2 %0, %1, %2, %3;" : "=l"(d) : "l"(a), "l"(b), "l"(c));
    return d;
}
__device__ __forceinline__ ull add2(ull a, ull b) {
    ull d;
    asm("add.rn.f32x2 %0, %1, %2;" : "=l"(d) : "l"(a), "l"(b));
    return d;
}
__device__ __forceinline__ ull dup2(float a) {
    ull d; unsigned int u = __float_as_uint(a);
    asm("mov.b64 %0, {%1, %1};" : "=l"(d) : "r"(u));
    return d;
}
#define NEG1_PAIR 0xBF800000BF800000ULL   // {-1.0f, -1.0f}

// ================= 1) conv3x3 + bias + relu as implicit GEMM ================
// C[m,n] = sum_k W[m,k]*im2col(X)[k,n]; 128x128x8 tile, 256 thr, 8x8/thread,
// all math in fma.rn.f32x2 (FFMA2). Accumulation: 32-k chunks in ch[] with
// cascaded Neumaier error-feedback merge into acc[] (Kahan-quality, no 3rd
// register array).
__global__ __launch_bounds__(256, 1) void conv3x3_kernel(
    const float* __restrict__ x, const float* __restrict__ wgt,
    const float* __restrict__ bias)
{
    __shared__ float As[2][BK][BM];
    __shared__ float Bs[2][BK][BN];

    const int tid = threadIdx.x;
    const int n0  = blockIdx.x * BN;
    const int m0  = blockIdx.y * BM;
    const int tx  = tid & 15;
    const int ty  = tid >> 4;
    const int tx4 = tx * 4;
    const int ty4 = ty * 4;

    // --- A loader: thread loads float4 along k for one m-row ---
    const int a_m = tid >> 1;             // 0..127
    const int a_k = (tid & 1) * 4;        // 0 or 4
    const float* aptr = wgt + (size_t)(m0 + a_m) * KTOT + a_k;

    // --- B (im2col) loader: (b_k, 4 consecutive n) per thread ---
    const int b_k = tid >> 5;             // 0..7
    const int b_n = (tid & 31) * 4;       // 0..124
    int nbase[4], nyv[4], nxv[4];
    bool nok[4];
#pragma unroll
    for (int u = 0; u < 4; u++) {
        int n = n0 + b_n + u;
        nok[u] = (n < NPIX);
        int nc = nok[u] ? n : 0;
        int bi = nc / HWP;
        int p  = nc - bi * HWP;
        int y  = p / WW;
        nyv[u] = y;
        nxv[u] = p - y * WW;
        nbase[u] = bi * (CIN * HWP);
    }

    ull acc[8][4], ch[8][4];
#pragma unroll
    for (int i = 0; i < 8; i++)
#pragma unroll
        for (int jp = 0; jp < 4; jp++) { acc[i][jp] = 0ULL; ch[i][jp] = 0ULL; }

    // ---- prologue: load tile 0 and stage into buffer 0 ----
    {
        float4 av = *(const float4*)(aptr + 0);
        As[0][a_k + 0][a_m] = av.x;
        As[0][a_k + 1][a_m] = av.y;
        As[0][a_k + 2][a_m] = av.z;
        As[0][a_k + 3][a_m] = av.w;

        int kg = b_k;
        int ic = kg / 9;
        int rem = kg - ic * 9;
        int ky = rem / 3, kx = rem - (rem / 3) * 3;
        int dy = ky - 1, dx = kx - 1;
        float bv[4];
#pragma unroll
        for (int u = 0; u < 4; u++) {
            int iy = nyv[u] + dy;
            int ix = nxv[u] + dx;
            bool ok = nok[u] && ((unsigned)iy < (unsigned)HH) && ((unsigned)ix < (unsigned)WW);
            bv[u] = ok ? x[nbase[u] + ic * HWP + iy * WW + ix] : 0.0f;
        }
        *(float4*)&Bs[0][b_k][b_n] = make_float4(bv[0], bv[1], bv[2], bv[3]);
    }
    __syncthreads();

    for (int it = 0; it < CITERS; ++it) {
        const int buf = it & 1;
        const bool have_next = (it + 1 < CITERS);

        // ---- prefetch next tile into registers ----
        float4 areg_n = make_float4(0.f, 0.f, 0.f, 0.f);
        float breg_n[4] = {0.f, 0.f, 0.f, 0.f};
        if (have_next) {
            int k0n = (it + 1) * BK;
            areg_n = *(const float4*)(aptr + k0n);
            int kg = k0n + b_k;
            int ic = kg / 9;
            int rem = kg - ic * 9;
            int ky = rem / 3;
            int kx = rem - ky * 3;
            int dy = ky - 1, dx = kx - 1;
#pragma unroll
            for (int u = 0; u < 4; u++) {
                int iy = nyv[u] + dy;
                int ix = nxv[u] + dx;
                bool ok = nok[u] && ((unsigned)iy < (unsigned)HH) && ((unsigned)ix < (unsigned)WW);
                breg_n[u] = ok ? x[nbase[u] + ic * HWP + iy * WW + ix] : 0.0f;
            }
        }

        // ---- compute 8 k-steps from smem[buf] in FFMA2 ----
#pragma unroll
        for (int kk = 0; kk < BK; kk++) {
            float4 a0 = *(const float4*)&As[buf][kk][ty4];
            float4 a1 = *(const float4*)&As[buf][kk][64 + ty4];
            float4 b0 = *(const float4*)&Bs[buf][kk][tx4];
            float4 b1 = *(const float4*)&Bs[buf][kk][64 + tx4];
            ull bp[4];
            memcpy(&bp[0], &b0.x, 8); memcpy(&bp[1], &b0.z, 8);
            memcpy(&bp[2], &b1.x, 8); memcpy(&bp[3], &b1.z, 8);
            float av[8] = {a0.x, a0.y, a0.z, a0.w, a1.x, a1.y, a1.z, a1.w};
#pragma unroll
            for (int i = 0; i < 8; i++) {
                ull ad = dup2(av[i]);
#pragma unroll
                for (int jp = 0; jp < 4; jp++)
                    ch[i][jp] = fma2(ad, bp[jp], ch[i][jp]);
            }
        }

        // ---- every 32 k: Neumaier merge ch -> acc, error re-seeds ch ----
        if ((it & 3) == 3) {
#pragma unroll
            for (int i = 0; i < 8; i++)
#pragma unroll
                for (int jp = 0; jp < 4; jp++) {
                    ull t = add2(acc[i][jp], ch[i][jp]);
                    ull d = fma2(NEG1_PAIR, acc[i][jp], t);   // t - acc
                    ull e = fma2(NEG1_PAIR, d, ch[i][jp]);    // ch - d
                    acc[i][jp] = t;
                    ch[i][jp]  = e;
                }
        }

        // ---- stage next tile into the other buffer ----
        if (have_next) {
            As[buf ^ 1][a_k + 0][a_m] = areg_n.x;
            As[buf ^ 1][a_k + 1][a_m] = areg_n.y;
            As[buf ^ 1][a_k + 2][a_m] = areg_n.z;
            As[buf ^ 1][a_k + 3][a_m] = areg_n.w;
            *(float4*)&Bs[buf ^ 1][b_k][b_n] =
                make_float4(breg_n[0], breg_n[1], breg_n[2], breg_n[3]);
            __syncthreads();
        }
    }

    // fold remaining compensation
#pragma unroll
    for (int i = 0; i < 8; i++)
#pragma unroll
        for (int jp = 0; jp < 4; jp++) acc[i][jp] = add2(acc[i][jp], ch[i][jp]);

    // epilogue: +bias, relu, store to g_shared[b][oc][p]
#pragma unroll
    for (int i = 0; i < 8; i++) {
        int m = m0 + ((i < 4) ? (ty4 + i) : (64 + ty4 + (i - 4)));
        float bb = bias[m];
#pragma unroll
        for (int jp = 0; jp < 4; jp++) {
            float2 v;
            memcpy(&v, &acc[i][jp], 8);
            int ncol = (jp < 2) ? (tx4 + 2 * jp) : (64 + tx4 + 2 * (jp - 2));
            int n = n0 + ncol;
            if (n < NPIX) {
                int bi = n / HWP, p = n - bi * HWP;
                g_shared[((size_t)bi * OC + m) * HWP + p] = fmaxf(v.x + bb, 0.0f);
            }
            n++;
            if (n < NPIX) {
                int bi = n / HWP, p = n - bi * HWP;
                g_shared[((size_t)bi * OC + m) * HWP + p] = fmaxf(v.y + bb, 0.0f);
            }
        }
    }
}

// ======= 2) fused 1x1 heads + softmax + decode + clip + min-size mask =======
// block = 32 pixels x 8 row-groups (54 output rows: 0..17 cls, 18..53 reg)
// K=512 dot products: chunk-16 partial sums Kahan-merged (error ~3 eps).
__global__ __launch_bounds__(256) void head_kernel(
    const float* __restrict__ clsw, const float* __restrict__ clsb,
    const float* __restrict__ regw, const float* __restrict__ regb)
{
    __shared__ float vals[54][33];

    const int tid = threadIdx.x;
    const int px  = tid & 31;
    const int r0  = tid >> 5;          // 0..7
    const int n   = blockIdx.x * 32 + px;
    const int bi  = n / HWP;
    const int p   = n - bi * HWP;

    const float* act = g_shared + (size_t)bi * OC * HWP + p;

    const int gcount = (r0 < 6) ? 7 : 6;
    float acc[7], cmp[7], bias0[7];
    const float* wrow[7];
#pragma unroll
    for (int g = 0; g < 7; g++) {
        acc[g] = 0.0f; cmp[g] = 0.0f; bias0[g] = 0.0f; wrow[g] = clsw;
        if (g < gcount) {
            int r = r0 + 8 * g;
            if (r < 18) { bias0[g] = clsb[r];      wrow[g] = clsw + r * 512; }
            else        { bias0[g] = regb[r - 18]; wrow[g] = regw + (r - 18) * 512; }
        }
    }

    for (int k0 = 0; k0 < 512; k0 += 16) {
        float ch[7];
#pragma unroll
        for (int g = 0; g < 7; g++) ch[g] = 0.0f;
#pragma unroll
        for (int kk = 0; kk < 16; kk++) {
            float a = act[(size_t)(k0 + kk) * HWP];
#pragma unroll
            for (int g = 0; g < 7; g++)
                if (g < gcount) ch[g] += wrow[g][k0 + kk] * a;
        }
#pragma unroll
        for (int g = 0; g < 7; g++) {
            float y = ch[g] - cmp[g];
            float t = acc[g] + y;
            cmp[g] = (t - acc[g]) - y;
            acc[g] = t;
        }
    }
#pragma unroll
    for (int g = 0; g < 7; g++)
        if (g < gcount) vals[r0 + 8 * g][px] = acc[g] + bias0[g];
    __syncthreads();

    if (tid < 32) {
        // softmax over 18 cls channels (max-subtracted, matches jax.nn.softmax)
        float mx = vals[0][px];
#pragma unroll
        for (int c = 1; c < 18; c++) mx = fmaxf(mx, vals[c][px]);
        float sum = 0.0f;
#pragma unroll
        for (int c = 0; c < 18; c++) sum += expf(vals[c][px] - mx);

        int y  = p / WW;
        int xq = p - y * WW;
        float sy = (float)(y  * 16);
        float sx = (float)(xq * 16);

#pragma unroll
        for (int a = 0; a < 9; a++) {
            float score = expf(vals[2 * a + 1][px] - mx) / sum;
            float dy = vals[18 + 4 * a + 0][px];
            float dx = vals[18 + 4 * a + 1][px];
            float dh = vals[18 + 4 * a + 2][px];
            float dw = vals[18 + 4 * a + 3][px];

            float ay1 = sy + c_ab[a][0];
            float ax1 = sx + c_ab[a][1];
            float ay2 = sy + c_ab[a][2];
            float ax2 = sx + c_ab[a][3];
            float ah  = ay2 - ay1;
            float aw  = ax2 - ax1;
            float acy = ay1 + 0.5f * ah;
            float acx = ax1 + 0.5f * aw;
            float cy  = dy * ah + acy;
            float cx  = dx * aw + acx;
            float h2  = expf(dh) * ah;
            float w2  = expf(dw) * aw;
            float y1 = cy - 0.5f * h2, x1 = cx - 0.5f * w2;
            float y2 = cy + 0.5f * h2, x2 = cx + 0.5f * w2;
            // clip to image
            y1 = fminf(fmaxf(y1, 0.0f), IMG_HF);
            x1 = fminf(fmaxf(x1, 0.0f), IMG_WF);
            y2 = fminf(fmaxf(y2, 0.0f), IMG_HF);
            x2 = fminf(fmaxf(x2, 0.0f), IMG_WF);
            float hs = y2 - y1, ws = x2 - x1;
            if (!(hs >= MIN_SZ && ws >= MIN_SZ)) score = -INFINITY;

            int idx = bi * NANCH + p * 9 + a;
            g_boxes[idx]  = make_float4(y1, x1, y2, x2);
            g_scores[idx] = score;
        }
    }
}

// ================= 3) per-image top-6000 + greedy NMS =======================
__device__ __forceinline__ unsigned long long make_key(float s, int i) {
    unsigned int ub  = __float_as_uint(s);
    unsigned int ord = (ub & 0x80000000u) ? ~ub : (ub | 0x80000000u);
    return ((unsigned long long)ord << 32) |
           (unsigned long long)(0xFFFFFFFFu - (unsigned)i);
}

__global__ __launch_bounds__(1024) void nms_kernel(float* __restrict__ out)
{
    extern __shared__ char smraw[];
    unsigned long long* keys = (unsigned long long*)smraw;                 // 8192
    float* by1 = (float*)(smraw + PRE_PAD * 8);
    float* bx1 = by1 + CAND_PAD;
    float* by2 = bx1 + CAND_PAD;
    float* bx2 = by2 + CAND_PAD;
    float* bar = bx2 + CAND_PAD;
    float* bsc = bar + CAND_PAD;
    unsigned char* valid = (unsigned char*)(bsc + CAND_PAD);

    __shared__ unsigned int hist[256];
    __shared__ unsigned long long prefix_s;
    __shared__ int rank_s, cnt_s, sel_s, cur_s;

    const int img = blockIdx.x;
    const int tid = threadIdx.x;
    const float* sc = g_scores + img * NANCH;

    if (tid == 0) { prefix_s = 0ULL; rank_s = PRE; cnt_s = 0; cur_s = 0; }
    __syncthreads();

    // --- exact 64-bit radix-select of the PRE-th largest key (keys distinct) ---
    for (int byte = 7; byte >= 0; byte--) {
        if (tid < 256) hist[tid] = 0u;
        __syncthreads();
        unsigned long long pre = prefix_s;
        for (int i = tid; i < NANCH; i += 1024) {
            unsigned long long key = make_key(sc[i], i);
            bool match = (byte == 7) ||
                ((key >> ((byte + 1) * 8)) == (pre >> ((byte + 1) * 8)));
            if (match) atomicAdd(&hist[(unsigned)(key >> (byte * 8)) & 255u], 1u);
        }
        __syncthreads();
        if (tid == 0) {
            int rank = rank_s;
            int d = 255;
            for (; d > 0; d--) {
                int c = (int)hist[d];
                if (c >= rank) break;
                rank -= c;
            }
            rank_s   = rank;
            prefix_s = prefix_s | ((unsigned long long)(unsigned)d << (byte * 8));
        }
        __syncthreads();
    }
    const unsigned long long T = prefix_s;

    // --- compact the exactly-PRE keys >= T, pad to PRE_PAD ---
    for (int i = tid; i < NANCH; i += 1024) {
        unsigned long long key = make_key(sc[i], i);
        if (key >= T) {
            int pos = atomicAdd(&cnt_s, 1);
            if (pos < PRE_PAD) keys[pos] = key;
        }
    }
    __syncthreads();
    int cnt = cnt_s; if (cnt > PRE_PAD) cnt = PRE_PAD;
    for (int i = tid; i < PRE_PAD; i += 1024)
        if (i >= cnt) keys[i] = 0ULL;
    __syncthreads();

    // --- bitonic sort descending (8192 u64 keys in smem) ---
    for (int k = 2; k <= PRE_PAD; k <<= 1) {
        for (int j = k >> 1; j >= 1; j >>= 1) {
            for (int t = tid; t < PRE_PAD; t += 1024) {
                int l = t ^ j;
                if (l > t) {
                    unsigned long long a = keys[t], b = keys[l];
                    bool seg = ((t & k) == 0);
                    if (seg ? (a < b) : (a > b)) { keys[t] = b; keys[l] = a; }
                }
            }
            __syncthreads();
        }
    }

    // --- gather sorted candidates into SoA smem ---
    for (int jj = tid; jj < PRE; jj += 1024) {
        unsigned long long key = keys[jj];
        if (key == 0ULL) {  // safety: fewer than PRE real candidates
            by1[jj] = bx1[jj] = by2[jj] = bx2[jj] = bar[jj] = bsc[jj] = 0.0f;
            valid[jj] = 0;
            continue;
        }
        unsigned int low = (unsigned int)key;
        int i = (int)(0xFFFFFFFFu - low);
        float4 bx = g_boxes[img * NANCH + i];
        by1[jj] = bx.x; bx1[jj] = bx.y; by2[jj] = bx.z; bx2[jj] = bx.w;
        bar[jj] = fmaxf(bx.z - bx.x, 0.0f) * fmaxf(bx.w - bx.y, 0.0f);
        unsigned int ou = (unsigned int)(key >> 32);
        unsigned int fb = (ou & 0x80000000u) ? (ou & 0x7FFFFFFFu) : ~ou;
        float s = __uint_as_float(fb);
        bsc[jj]   = s;
        valid[jj] = isfinite(s) ? 1 : 0;
    }
    __syncthreads();

    // --- greedy NMS walk over the sorted list (== repeated argmax) ---
    float* o = out + (size_t)img * POST * 5;
    for (int t = 0; t < POST; t++) {
        if (tid == 0) {
            int c = cur_s;
            while (c < PRE && !valid[c]) c++;
            if (c < PRE) { valid[c] = 0; sel_s = c; cur_s = c + 1; }
            else sel_s = -1;
        }
        __syncthreads();
        int sel = sel_s;
        if (sel < 0) {   // out of valid candidates -> zero remaining rows
            for (int e = t * 5 + tid; e < POST * 5; e += 1024) o[e] = 0.0f;
            break;
        }
        float sy1 = by1[sel], sx1 = bx1[sel], sy2 = by2[sel], sx2 = bx2[sel];
        float sa  = bar[sel];
        for (int j = tid; j < PRE; j += 1024) {
            if (valid[j]) {
                float yy1 = fmaxf(sy1, by1[j]);
                float xx1 = fmaxf(sx1, bx1[j]);
                float yy2 = fminf(sy2, by2[j]);
                float xx2 = fminf(sx2, bx2[j]);
                float inter = fmaxf(yy2 - yy1, 0.0f) * fmaxf(xx2 - xx1, 0.0f);
                float iou = inter / (bar[j] + sa - inter + 1e-9f);
                if (iou > NMS_T) valid[j] = 0;
            }
        }
        if (tid == 0) {
            o[t * 5 + 0] = sy1; o[t * 5 + 1] = sx1;
            o[t * 5 + 2] = sy2; o[t * 5 + 3] = sx2;
            o[t * 5 + 4] = bsc[sel];
        }
        __syncthreads();
    }
}

// ============================== launch ======================================
extern "C" void kernel_launch(void* const* d_in, const int* in_sizes, int n_in,
                              void* d_out, int out_size)
{
    const float* x  = (const float*)d_in[0];
    const float* sw = (const float*)d_in[1];
    const float* sb = (const float*)d_in[2];
    const float* cw = (const float*)d_in[3];
    const float* cb = (const float*)d_in[4];
    const float* rw = (const float*)d_in[5];
    const float* rb = (const float*)d_in[6];
    float* out = (float*)d_out;

    conv3x3_kernel<<<dim3((NPIX + BN - 1) / BN, OC / BM), 256>>>(x, sw, sb);
    head_kernel<<<NPIX / 32, 256>>>(cw, cb, rw, rb);

    const int nms_smem = PRE_PAD * 8 + 6 * CAND_PAD * 4 + CAND_PAD;  // 215936 B
    cudaFuncSetAttribute(nms_kernel,
                         cudaFuncAttributeMaxDynamicSharedMemorySize, nms_smem);
    nms_kernel<<<BATCH, 1024, nms_smem>>>(out);
}